// round 11
// baseline (speedup 1.0000x reference)
#include <cuda_runtime.h>

#define BATCH   262144
#define NIND    32
#define NDEP    16
#define EPSV    1e-7f
#define ITERS   2

typedef unsigned long long u64;

// ---- packed f32x2 helpers (Blackwell sm_103a) ----
__device__ __forceinline__ u64 pack2(float a, float b) {
    u64 r; asm("mov.b64 %0, {%1, %2};" : "=l"(r) : "f"(a), "f"(b)); return r;
}
__device__ __forceinline__ u64 dup2(float a) {
    u64 r; asm("mov.b64 %0, {%1, %1};" : "=l"(r) : "f"(a)); return r;
}
__device__ __forceinline__ void unpack2(u64 v, float &a, float &b) {
    asm("mov.b64 {%0, %1}, %2;" : "=f"(a), "=f"(b) : "l"(v));
}
__device__ __forceinline__ u64 ffma2(u64 a, u64 b, u64 c) {
    u64 d; asm("fma.rn.f32x2 %0, %1, %2, %3;" : "=l"(d) : "l"(a), "l"(b), "l"(c));
    return d;
}
__device__ __forceinline__ u64 mul2(u64 a, u64 b) {
    u64 d; asm("mul.rn.f32x2 %0, %1, %2;" : "=l"(d) : "l"(a), "l"(b));
    return d;
}
__device__ __forceinline__ float frcp(float x) {
    float r; asm("rcp.approx.f32 %0, %1;" : "=f"(r) : "f"(x)); return r;
}

// Pre-transformed weights: row-paired u64 for direct f32x2 operands.
struct CWeights {
    ulonglong2 W2[2 * NIND][4];   // [k][q2]: rows (4q2..4q2+3) paired; k<32->Bmat, else Theta
    ulonglong2 L2[NIND][4];       // Lam
    ulonglong2 Off2[NDEP][4];     // column j, rows paired; +Gamma off-diag, 0 diag
    u64 Gd2[8];                   // (1+eps - Gamma_ii) pairs
    u64 Ups2[8];
};

__device__ CWeights g_scratch;    // written by prep kernel
__constant__ CWeights cw;         // copied from g_scratch before main kernel

// ---- prep kernel: transform raw weights into g_scratch layout ----
__global__ void prep_kernel(const float* __restrict__ Ups, const float* __restrict__ Bm,
                            const float* __restrict__ Th,  const float* __restrict__ Ga,
                            const float* __restrict__ La)
{
    const int tid = threadIdx.x;
    for (int idx = tid; idx < 2 * NIND * 8; idx += 64) {
        int k = idx >> 3, j2 = idx & 7;
        int r0 = 2 * j2, r1 = r0 + 1;
        float w0, w1;
        if (k < NIND) { w0 = Bm[r0 * NIND + k];          w1 = Bm[r1 * NIND + k]; }
        else          { w0 = Th[r0 * NIND + (k - NIND)]; w1 = Th[r1 * NIND + (k - NIND)]; }
        ((u64*)&g_scratch.W2[k][0])[j2] = pack2(w0, w1);
    }
    for (int idx = tid; idx < NIND * 8; idx += 64) {
        int k = idx >> 3, j2 = idx & 7;
        ((u64*)&g_scratch.L2[k][0])[j2] =
            pack2(La[(2 * j2) * NIND + k], La[(2 * j2 + 1) * NIND + k]);
    }
    for (int idx = tid; idx < NDEP * 8; idx += 64) {
        int j = idx >> 3, i2 = idx & 7;
        int i0 = 2 * i2, i1 = i0 + 1;
        float v0 = (i0 == j) ? 0.0f : Ga[i0 * NDEP + j];
        float v1 = (i1 == j) ? 0.0f : Ga[i1 * NDEP + j];
        ((u64*)&g_scratch.Off2[j][0])[i2] = pack2(v0, v1);
    }
    if (tid < 8) {
        g_scratch.Ups2[tid] = pack2(Ups[2 * tid], Ups[2 * tid + 1]);
        g_scratch.Gd2[tid]  = pack2(1.0f + EPSV - Ga[(2 * tid) * NDEP + 2 * tid],
                                    1.0f + EPSV - Ga[(2 * tid + 1) * NDEP + 2 * tid + 1]);
    }
}

#define ROWSTRIDE 33   // floats per staged row (conflict-free scalar access)
#define TPB       64   // threads per block
#define EPT       2    // elements per thread (phase-1 weight amortization)
#define PARKSTR   17   // u64 stride for parked state (conflict-balanced)

// Solve one element (phases 2+3) from its rhs/dd; writes 64B output.
// Active register set ~64 regs: rhs(16) + inv(16) + y(16) + acc(16 transient).
__device__ __forceinline__ void solve_one(const u64* __restrict__ rhs,
                                          const u64* __restrict__ dd,
                                          float* __restrict__ o)
{
    u64 inv[8], y[8];
#pragma unroll
    for (int q = 0; q < 8; ++q) {
        float g0, g1; unpack2(cw.Gd2[q], g0, g1);
        float d0, d1; unpack2(dd[q], d0, d1);
        inv[q] = pack2(frcp(g0 - d0), frcp(g1 - d1));
        y[q]   = mul2(inv[q], rhs[q]);
    }
#pragma unroll
    for (int it = 0; it < ITERS; ++it) {
        u64 acc[8];
#pragma unroll
        for (int q = 0; q < 8; ++q) acc[q] = rhs[q];
#pragma unroll
        for (int j = 0; j < NDEP; ++j) {
            float a0, a1; unpack2(y[j >> 1], a0, a1);
            u64 yd = dup2((j & 1) ? a1 : a0);
#pragma unroll
            for (int q2 = 0; q2 < 4; ++q2) {
                ulonglong2 ow = cw.Off2[j][q2];
                acc[2 * q2]     = ffma2(yd, ow.x, acc[2 * q2]);
                acc[2 * q2 + 1] = ffma2(yd, ow.y, acc[2 * q2 + 1]);
            }
        }
#pragma unroll
        for (int q = 0; q < 8; ++q) y[q] = mul2(inv[q], acc[q]);
    }
    ulonglong2* v = (ulonglong2*)o;
#pragma unroll
    for (int q = 0; q < 4; ++q) v[q] = make_ulonglong2(y[2 * q], y[2 * q + 1]);
}

// TWO elements per thread in phase 1 (amortizes W2 constant loads; L2 rides
// the smem crossbar in parallel). Element B's rhs/dd then PARK in smem while
// phases 2-3 run one element at a time (~64 live regs) -> 9 CTAs/SM.
__global__ __launch_bounds__(TPB, 9)
void clefo_kernel(const float* __restrict__ X, const float* __restrict__ Z,
                  const CWeights* __restrict__ gw,
                  float* __restrict__ out)
{
    __shared__ float sStage[TPB * EPT * ROWSTRIDE]; // X/Z slab; later: parking
    __shared__ ulonglong2 sL2[NIND][4];             // Lam on the crossbar

    const int tid = threadIdx.x;
    const size_t base = (size_t)blockIdx.x * (TPB * EPT);

    // ---- stage X slab (coalesced) + L2 weights into smem ----
    {
        const float4* src = (const float4*)(X + base * NIND);
#pragma unroll
        for (int i = 0; i < 8 * EPT; ++i) {
            int idx = tid + TPB * i;
            float4 v = src[idx];
            int row = idx >> 3, c0 = (idx & 7) << 2;
            float* dst = &sStage[row * ROWSTRIDE + c0];
            dst[0] = v.x; dst[1] = v.y; dst[2] = v.z; dst[3] = v.w;
        }
        // 128 ulonglong2 over 64 threads
        ((ulonglong2*)sL2)[tid]      = ((const ulonglong2*)gw->L2)[tid];
        ((ulonglong2*)sL2)[tid + 64] = ((const ulonglong2*)gw->L2)[tid + 64];
    }
    __syncthreads();

    const float* row0 = &sStage[(tid      ) * ROWSTRIDE];
    const float* row1 = &sStage[(tid + TPB) * ROWSTRIDE];

    // ---- Phase 1a: X-loop  (rhs += Bm*x ; d = La*x), rows packed in pairs
    u64 rhs0[8], rhs1[8], dd0[8], dd1[8];
#pragma unroll
    for (int q = 0; q < 8; ++q) {
        rhs0[q] = cw.Ups2[q]; rhs1[q] = cw.Ups2[q];
        dd0[q] = 0ull;        dd1[q] = 0ull;
    }

#pragma unroll
    for (int k = 0; k < NIND; ++k) {
        u64 xd0 = dup2(row0[k]);
        u64 xd1 = dup2(row1[k]);
#pragma unroll
        for (int q2 = 0; q2 < 4; ++q2) {
            ulonglong2 w = cw.W2[k][q2];              // constant port
            rhs0[2 * q2]     = ffma2(xd0, w.x, rhs0[2 * q2]);
            rhs0[2 * q2 + 1] = ffma2(xd0, w.y, rhs0[2 * q2 + 1]);
            rhs1[2 * q2]     = ffma2(xd1, w.x, rhs1[2 * q2]);
            rhs1[2 * q2 + 1] = ffma2(xd1, w.y, rhs1[2 * q2 + 1]);
            ulonglong2 l = sL2[k][q2];                // smem crossbar (parallel)
            dd0[2 * q2]      = ffma2(xd0, l.x, dd0[2 * q2]);
            dd0[2 * q2 + 1]  = ffma2(xd0, l.y, dd0[2 * q2 + 1]);
            dd1[2 * q2]      = ffma2(xd1, l.x, dd1[2 * q2]);
            dd1[2 * q2 + 1]  = ffma2(xd1, l.y, dd1[2 * q2 + 1]);
        }
    }
    __syncthreads();

    // ---- stage Z slab (reuse buffer) ----
    {
        const float4* src = (const float4*)(Z + base * NIND);
#pragma unroll
        for (int i = 0; i < 8 * EPT; ++i) {
            int idx = tid + TPB * i;
            float4 v = src[idx];
            int r = idx >> 3, c0 = (idx & 7) << 2;
            float* dst = &sStage[r * ROWSTRIDE + c0];
            dst[0] = v.x; dst[1] = v.y; dst[2] = v.z; dst[3] = v.w;
        }
    }
    __syncthreads();

    // ---- Phase 1b: Z-loop  (rhs += Theta*z)
#pragma unroll
    for (int kz = 0; kz < NIND; ++kz) {
        int k = NIND + kz;
        u64 xd0 = dup2(row0[kz]);
        u64 xd1 = dup2(row1[kz]);
#pragma unroll
        for (int q2 = 0; q2 < 4; ++q2) {
            ulonglong2 w = cw.W2[k][q2];
            rhs0[2 * q2]     = ffma2(xd0, w.x, rhs0[2 * q2]);
            rhs0[2 * q2 + 1] = ffma2(xd0, w.y, rhs0[2 * q2 + 1]);
            rhs1[2 * q2]     = ffma2(xd1, w.x, rhs1[2 * q2]);
            rhs1[2 * q2 + 1] = ffma2(xd1, w.y, rhs1[2 * q2 + 1]);
        }
    }
    __syncthreads();   // all Z reads done before parking clobbers the slab

    // ---- Park element B's state in smem (frees 32 regs for the solve) ----
    {
        u64* park = (u64*)sStage + (size_t)tid * PARKSTR;
#pragma unroll
        for (int q = 0; q < 8; ++q) { park[q] = rhs1[q]; park[8 + q] = dd1[q]; }
    }

    // ---- Solve element A (phases 2+3, ~64 live regs) ----
    solve_one(rhs0, dd0, out + (base + tid) * NDEP);

    // ---- Unpark and solve element B ----
    {
        u64 rhsb[8], ddb[8];
        const u64* park = (const u64*)sStage + (size_t)tid * PARKSTR;
#pragma unroll
        for (int q = 0; q < 8; ++q) { rhsb[q] = park[q]; ddb[q] = park[8 + q]; }
        solve_one(rhsb, ddb, out + (base + TPB + tid) * NDEP);
    }
}

extern "C" void kernel_launch(void* const* d_in, const int* in_sizes, int n_in,
                              void* d_out, int out_size)
{
    const float* X  = (const float*)d_in[0];
    const float* Z  = (const float*)d_in[1];
    const float* Up = (const float*)d_in[2];
    const float* Bm = (const float*)d_in[3];
    const float* Th = (const float*)d_in[4];
    const float* Ga = (const float*)d_in[5];
    const float* La = (const float*)d_in[6];
    float* out = (float*)d_out;

    // 1) transform weights into device scratch
    prep_kernel<<<1, 64>>>(Up, Bm, Th, Ga, La);

    // 2) copy transformed weights into the constant bank (D2D, capturable)
    void* sp = nullptr;
    cudaGetSymbolAddress(&sp, g_scratch);
    cudaMemcpyToSymbolAsync(cw, sp, sizeof(CWeights), 0,
                            cudaMemcpyDeviceToDevice, 0);

    // 3) main kernel
    const int blocks = BATCH / (TPB * EPT);
    clefo_kernel<<<blocks, TPB>>>(X, Z, (const CWeights*)sp, out);
}

// round 12
// speedup vs baseline: 1.3500x; 1.3500x over previous
#include <cuda_runtime.h>

#define BATCH   262144
#define NIND    32
#define NDEP    16
#define EPSV    1e-7f
#define ITERS   2

typedef unsigned long long u64;

// ---- packed f32x2 helpers (Blackwell sm_103a) ----
__device__ __forceinline__ u64 pack2(float a, float b) {
    u64 r; asm("mov.b64 %0, {%1, %2};" : "=l"(r) : "f"(a), "f"(b)); return r;
}
__device__ __forceinline__ u64 dup2(float a) {
    u64 r; asm("mov.b64 %0, {%1, %1};" : "=l"(r) : "f"(a)); return r;
}
__device__ __forceinline__ void unpack2(u64 v, float &a, float &b) {
    asm("mov.b64 {%0, %1}, %2;" : "=f"(a), "=f"(b) : "l"(v));
}
__device__ __forceinline__ u64 ffma2(u64 a, u64 b, u64 c) {
    u64 d; asm("fma.rn.f32x2 %0, %1, %2, %3;" : "=l"(d) : "l"(a), "l"(b), "l"(c));
    return d;
}
__device__ __forceinline__ u64 mul2(u64 a, u64 b) {
    u64 d; asm("mul.rn.f32x2 %0, %1, %2;" : "=l"(d) : "l"(a), "l"(b));
    return d;
}
__device__ __forceinline__ float frcp(float x) {
    float r; asm("rcp.approx.f32 %0, %1;" : "=f"(r) : "f"(x)); return r;
}

// Pre-transformed weights: row-paired u64 for direct f32x2 operands.
struct CWeights {
    ulonglong2 W2[2 * NIND][4];   // [k][q2]: rows (4q2..4q2+3) paired; k<32->Bmat, else Theta
    ulonglong2 L2[NIND][4];       // Lam
    ulonglong2 Off2[NDEP][4];     // column j, rows paired; +Gamma off-diag, 0 diag
    u64 Gd2[8];                   // (1+eps - Gamma_ii) pairs
    u64 Ups2[8];
};

__device__ CWeights g_scratch;    // written by prep kernel
__constant__ CWeights cw;         // copied from g_scratch before main kernel

// ---- prep kernel: transform raw weights into g_scratch layout ----
__global__ void prep_kernel(const float* __restrict__ Ups, const float* __restrict__ Bm,
                            const float* __restrict__ Th,  const float* __restrict__ Ga,
                            const float* __restrict__ La)
{
    const int tid = threadIdx.x;
    for (int idx = tid; idx < 2 * NIND * 8; idx += 64) {
        int k = idx >> 3, j2 = idx & 7;
        int r0 = 2 * j2, r1 = r0 + 1;
        float w0, w1;
        if (k < NIND) { w0 = Bm[r0 * NIND + k];          w1 = Bm[r1 * NIND + k]; }
        else          { w0 = Th[r0 * NIND + (k - NIND)]; w1 = Th[r1 * NIND + (k - NIND)]; }
        ((u64*)&g_scratch.W2[k][0])[j2] = pack2(w0, w1);
    }
    for (int idx = tid; idx < NIND * 8; idx += 64) {
        int k = idx >> 3, j2 = idx & 7;
        ((u64*)&g_scratch.L2[k][0])[j2] =
            pack2(La[(2 * j2) * NIND + k], La[(2 * j2 + 1) * NIND + k]);
    }
    for (int idx = tid; idx < NDEP * 8; idx += 64) {
        int j = idx >> 3, i2 = idx & 7;
        int i0 = 2 * i2, i1 = i0 + 1;
        float v0 = (i0 == j) ? 0.0f : Ga[i0 * NDEP + j];
        float v1 = (i1 == j) ? 0.0f : Ga[i1 * NDEP + j];
        ((u64*)&g_scratch.Off2[j][0])[i2] = pack2(v0, v1);
    }
    if (tid < 8) {
        g_scratch.Ups2[tid] = pack2(Ups[2 * tid], Ups[2 * tid + 1]);
        g_scratch.Gd2[tid]  = pack2(1.0f + EPSV - Ga[(2 * tid) * NDEP + 2 * tid],
                                    1.0f + EPSV - Ga[(2 * tid + 1) * NDEP + 2 * tid + 1]);
    }
}

#define ROWSTRIDE 33   // floats per staged row (conflict-free scalar access)
#define TPB       128  // threads per block, one element each

// ONE batch element per thread (R8 base: regs 80, occ 34%, issue 48%).
// Port split fix for R8's LDC-port floor: W2 from __constant__ (LDC port,
// 256/warp), L2+Off2 from shared (broadcast LDS.128 on the crossbar,
// 256/warp). The two load streams run on independent ports in parallel.
__global__ __launch_bounds__(TPB, 6)
void clefo_kernel(const float* __restrict__ X, const float* __restrict__ Z,
                  const CWeights* __restrict__ gw,
                  float* __restrict__ out)
{
    __shared__ float sStage[TPB * ROWSTRIDE];   // one block-slab of X or Z (reused)
    __shared__ ulonglong2 sL2[NIND][4];         // Lam on the crossbar
    __shared__ ulonglong2 sOff2[NDEP][4];       // Neumann weights on the crossbar

    const int tid = threadIdx.x;
    const size_t base = (size_t)blockIdx.x * TPB;

    // ---- stage X slab (coalesced) + L2/Off2 weights into smem ----
    {
        const float4* src = (const float4*)(X + base * NIND);
#pragma unroll
        for (int i = 0; i < 8; ++i) {
            int idx = tid + TPB * i;                 // float4 index in slab
            float4 v = src[idx];
            int row = idx >> 3, c0 = (idx & 7) << 2;
            float* dst = &sStage[row * ROWSTRIDE + c0];
            dst[0] = v.x; dst[1] = v.y; dst[2] = v.z; dst[3] = v.w;
        }
        // L2: 128 ulonglong2; Off2: 64 ulonglong2 — one/two per thread
        ((ulonglong2*)sL2)[tid] = ((const ulonglong2*)gw->L2)[tid];
        if (tid < 64)
            ((ulonglong2*)sOff2)[tid] = ((const ulonglong2*)gw->Off2)[tid];
    }
    __syncthreads();

    const float* row = &sStage[tid * ROWSTRIDE];

    // ---- Phase 1a: X-loop  (rhs += Bm*x ; d = La*x), rows packed in pairs
    u64 rhs[8], dd[8];
#pragma unroll
    for (int q = 0; q < 8; ++q) { rhs[q] = cw.Ups2[q]; dd[q] = 0ull; }

#pragma unroll
    for (int k = 0; k < NIND; ++k) {
        u64 xd = dup2(row[k]);
#pragma unroll
        for (int q2 = 0; q2 < 4; ++q2) {
            ulonglong2 w = cw.W2[k][q2];             // constant port
            rhs[2 * q2]     = ffma2(xd, w.x, rhs[2 * q2]);
            rhs[2 * q2 + 1] = ffma2(xd, w.y, rhs[2 * q2 + 1]);
            ulonglong2 l = sL2[k][q2];               // smem crossbar (parallel)
            dd[2 * q2]      = ffma2(xd, l.x, dd[2 * q2]);
            dd[2 * q2 + 1]  = ffma2(xd, l.y, dd[2 * q2 + 1]);
        }
    }
    __syncthreads();

    // ---- stage Z slab (reuse buffer) ----
    {
        const float4* src = (const float4*)(Z + base * NIND);
#pragma unroll
        for (int i = 0; i < 8; ++i) {
            int idx = tid + TPB * i;
            float4 v = src[idx];
            int r = idx >> 3, c0 = (idx & 7) << 2;
            float* dst = &sStage[r * ROWSTRIDE + c0];
            dst[0] = v.x; dst[1] = v.y; dst[2] = v.z; dst[3] = v.w;
        }
    }
    __syncthreads();

    // ---- Phase 1b: Z-loop  (rhs += Theta*z)
#pragma unroll
    for (int kz = 0; kz < NIND; ++kz) {
        int k = NIND + kz;
        u64 xd = dup2(row[kz]);
#pragma unroll
        for (int q2 = 0; q2 < 4; ++q2) {
            ulonglong2 w = cw.W2[k][q2];
            rhs[2 * q2]     = ffma2(xd, w.x, rhs[2 * q2]);
            rhs[2 * q2 + 1] = ffma2(xd, w.y, rhs[2 * q2 + 1]);
        }
    }

    // ---- Phase 2: Dg_i = (1+eps - Gamma_ii) - d_i ; inv = 1/Dg ; y0 = inv*rhs
    u64 inv[8], y[8];
#pragma unroll
    for (int q = 0; q < 8; ++q) {
        float g0, g1; unpack2(cw.Gd2[q], g0, g1);
        float d0, d1; unpack2(dd[q], d0, d1);
        inv[q] = pack2(frcp(g0 - d0), frcp(g1 - d1));
        y[q]   = mul2(inv[q], rhs[q]);
    }

    // ---- Phase 3: Neumann iterations  acc = rhs + GammaOff*y ; y = inv (*) acc
    // Off2 from smem (crossbar) — keeps the constant port free.
#pragma unroll
    for (int it = 0; it < ITERS; ++it) {
        u64 acc[8];
#pragma unroll
        for (int q = 0; q < 8; ++q) acc[q] = rhs[q];
#pragma unroll
        for (int j = 0; j < NDEP; ++j) {
            float a0, a1; unpack2(y[j >> 1], a0, a1);
            u64 yd = dup2((j & 1) ? a1 : a0);
#pragma unroll
            for (int q2 = 0; q2 < 4; ++q2) {
                ulonglong2 o = sOff2[j][q2];
                acc[2 * q2]     = ffma2(yd, o.x, acc[2 * q2]);
                acc[2 * q2 + 1] = ffma2(yd, o.y, acc[2 * q2 + 1]);
            }
        }
#pragma unroll
        for (int q = 0; q < 8; ++q) y[q] = mul2(inv[q], acc[q]);
    }

    // ---- Store: row-packed pairs are already in output order -> STG.128
    ulonglong2* ov = (ulonglong2*)(out + (base + tid) * NDEP);
#pragma unroll
    for (int q = 0; q < 4; ++q) ov[q] = make_ulonglong2(y[2 * q], y[2 * q + 1]);
}

extern "C" void kernel_launch(void* const* d_in, const int* in_sizes, int n_in,
                              void* d_out, int out_size)
{
    const float* X  = (const float*)d_in[0];
    const float* Z  = (const float*)d_in[1];
    const float* Up = (const float*)d_in[2];
    const float* Bm = (const float*)d_in[3];
    const float* Th = (const float*)d_in[4];
    const float* Ga = (const float*)d_in[5];
    const float* La = (const float*)d_in[6];
    float* out = (float*)d_out;

    // 1) transform weights into device scratch
    prep_kernel<<<1, 64>>>(Up, Bm, Th, Ga, La);

    // 2) copy transformed weights into the constant bank (D2D, capturable)
    void* sp = nullptr;
    cudaGetSymbolAddress(&sp, g_scratch);
    cudaMemcpyToSymbolAsync(cw, sp, sizeof(CWeights), 0,
                            cudaMemcpyDeviceToDevice, 0);

    // 3) main kernel: one element per thread
    const int blocks = BATCH / TPB;
    clefo_kernel<<<blocks, TPB>>>(X, Z, (const CWeights*)sp, out);
}

// round 13
// speedup vs baseline: 1.8068x; 1.3383x over previous
#include <cuda_runtime.h>

#define BATCH   262144
#define NIND    32
#define NDEP    16
#define EPSV    1e-7f
#define ITERS   2

typedef unsigned long long u64;

// ---- packed f32x2 helpers (Blackwell sm_103a) ----
__device__ __forceinline__ u64 pack2(float a, float b) {
    u64 r; asm("mov.b64 %0, {%1, %2};" : "=l"(r) : "f"(a), "f"(b)); return r;
}
__device__ __forceinline__ u64 dup2(float a) {
    u64 r; asm("mov.b64 %0, {%1, %1};" : "=l"(r) : "f"(a)); return r;
}
__device__ __forceinline__ void unpack2(u64 v, float &a, float &b) {
    asm("mov.b64 {%0, %1}, %2;" : "=f"(a), "=f"(b) : "l"(v));
}
__device__ __forceinline__ u64 ffma2(u64 a, u64 b, u64 c) {
    u64 d; asm("fma.rn.f32x2 %0, %1, %2, %3;" : "=l"(d) : "l"(a), "l"(b), "l"(c));
    return d;
}
__device__ __forceinline__ u64 mul2(u64 a, u64 b) {
    u64 d; asm("mul.rn.f32x2 %0, %1, %2;" : "=l"(d) : "l"(a), "l"(b));
    return d;
}
__device__ __forceinline__ float frcp(float x) {
    float r; asm("rcp.approx.f32 %0, %1;" : "=f"(r) : "f"(x)); return r;
}

// Pre-transformed weights: row-paired u64 for direct f32x2 operands.
struct CWeights {
    ulonglong2 W2[2 * NIND][4];   // [k][q2]: rows (4q2..4q2+3) paired; k<32->Bmat, else Theta
    ulonglong2 L2[NIND][4];       // Lam
    ulonglong2 Off2[NDEP][4];     // column j, rows paired; +Gamma off-diag, 0 diag
    u64 Gd2[8];                   // (1+eps - Gamma_ii) pairs
    u64 Ups2[8];
};

__device__ CWeights g_scratch;    // written by prep kernel
__constant__ CWeights cw;         // copied from g_scratch before main kernel

// ---- prep kernel: transform raw weights into g_scratch layout ----
__global__ void prep_kernel(const float* __restrict__ Ups, const float* __restrict__ Bm,
                            const float* __restrict__ Th,  const float* __restrict__ Ga,
                            const float* __restrict__ La)
{
    const int tid = threadIdx.x;
    for (int idx = tid; idx < 2 * NIND * 8; idx += 64) {
        int k = idx >> 3, j2 = idx & 7;
        int r0 = 2 * j2, r1 = r0 + 1;
        float w0, w1;
        if (k < NIND) { w0 = Bm[r0 * NIND + k];          w1 = Bm[r1 * NIND + k]; }
        else          { w0 = Th[r0 * NIND + (k - NIND)]; w1 = Th[r1 * NIND + (k - NIND)]; }
        ((u64*)&g_scratch.W2[k][0])[j2] = pack2(w0, w1);
    }
    for (int idx = tid; idx < NIND * 8; idx += 64) {
        int k = idx >> 3, j2 = idx & 7;
        ((u64*)&g_scratch.L2[k][0])[j2] =
            pack2(La[(2 * j2) * NIND + k], La[(2 * j2 + 1) * NIND + k]);
    }
    for (int idx = tid; idx < NDEP * 8; idx += 64) {
        int j = idx >> 3, i2 = idx & 7;
        int i0 = 2 * i2, i1 = i0 + 1;
        float v0 = (i0 == j) ? 0.0f : Ga[i0 * NDEP + j];
        float v1 = (i1 == j) ? 0.0f : Ga[i1 * NDEP + j];
        ((u64*)&g_scratch.Off2[j][0])[i2] = pack2(v0, v1);
    }
    if (tid < 8) {
        g_scratch.Ups2[tid] = pack2(Ups[2 * tid], Ups[2 * tid + 1]);
        g_scratch.Gd2[tid]  = pack2(1.0f + EPSV - Ga[(2 * tid) * NDEP + 2 * tid],
                                    1.0f + EPSV - Ga[(2 * tid + 1) * NDEP + 2 * tid + 1]);
    }
}

#define ROWSTRIDE 33   // floats per staged row (conflict-free scalar access)
#define TPB       128  // threads per block, one element each

// ONE batch element per thread (R8 base: regs 80, occ 34%, exposure 1.28).
// Port split per calibrated model (LDC.128=2cyc, LDS.128=4cyc per warp-instr):
//   constant port: W2 + L2 + Ups  (384 loads/thread -> 22.7us floor)
//   L1/smem path:  Off2 + Gd      (136 loads/thread -> ~16us floor + staging)
// The streams run on independent paths; binding floor drops 30 -> ~23us.
__global__ __launch_bounds__(TPB, 5)
void clefo_kernel(const float* __restrict__ X, const float* __restrict__ Z,
                  const CWeights* __restrict__ gw,
                  float* __restrict__ out)
{
    __shared__ float sStage[TPB * ROWSTRIDE];   // one block-slab of X or Z (reused)
    __shared__ ulonglong2 sOff2[NDEP][4];       // Neumann weights on the L1 path
    __shared__ u64 sGd2[8];

    const int tid = threadIdx.x;
    const size_t base = (size_t)blockIdx.x * TPB;

    // ---- stage X slab (coalesced) + Off2/Gd into smem ----
    {
        const float4* src = (const float4*)(X + base * NIND);
#pragma unroll
        for (int i = 0; i < 8; ++i) {
            int idx = tid + TPB * i;                 // float4 index in slab
            float4 v = src[idx];
            int row = idx >> 3, c0 = (idx & 7) << 2;
            float* dst = &sStage[row * ROWSTRIDE + c0];
            dst[0] = v.x; dst[1] = v.y; dst[2] = v.z; dst[3] = v.w;
        }
        if (tid < 64)
            ((ulonglong2*)sOff2)[tid] = ((const ulonglong2*)gw->Off2)[tid];
        else if (tid < 72)
            sGd2[tid - 64] = gw->Gd2[tid - 64];
    }
    __syncthreads();

    const float* row = &sStage[tid * ROWSTRIDE];

    // ---- Phase 1a: X-loop  (rhs += Bm*x ; d = La*x), rows packed in pairs
    u64 rhs[8], dd[8];
#pragma unroll
    for (int q = 0; q < 8; ++q) { rhs[q] = cw.Ups2[q]; dd[q] = 0ull; }

#pragma unroll
    for (int k = 0; k < NIND; ++k) {
        u64 xd = dup2(row[k]);
#pragma unroll
        for (int q2 = 0; q2 < 4; ++q2) {
            ulonglong2 w = cw.W2[k][q2];             // constant port
            rhs[2 * q2]     = ffma2(xd, w.x, rhs[2 * q2]);
            rhs[2 * q2 + 1] = ffma2(xd, w.y, rhs[2 * q2 + 1]);
            ulonglong2 l = cw.L2[k][q2];             // constant port
            dd[2 * q2]      = ffma2(xd, l.x, dd[2 * q2]);
            dd[2 * q2 + 1]  = ffma2(xd, l.y, dd[2 * q2 + 1]);
        }
    }
    __syncthreads();

    // ---- stage Z slab (reuse buffer) ----
    {
        const float4* src = (const float4*)(Z + base * NIND);
#pragma unroll
        for (int i = 0; i < 8; ++i) {
            int idx = tid + TPB * i;
            float4 v = src[idx];
            int r = idx >> 3, c0 = (idx & 7) << 2;
            float* dst = &sStage[r * ROWSTRIDE + c0];
            dst[0] = v.x; dst[1] = v.y; dst[2] = v.z; dst[3] = v.w;
        }
    }
    __syncthreads();

    // ---- Phase 1b: Z-loop  (rhs += Theta*z)
#pragma unroll
    for (int kz = 0; kz < NIND; ++kz) {
        int k = NIND + kz;
        u64 xd = dup2(row[kz]);
#pragma unroll
        for (int q2 = 0; q2 < 4; ++q2) {
            ulonglong2 w = cw.W2[k][q2];
            rhs[2 * q2]     = ffma2(xd, w.x, rhs[2 * q2]);
            rhs[2 * q2 + 1] = ffma2(xd, w.y, rhs[2 * q2 + 1]);
        }
    }

    // ---- Phase 2: Dg_i = (1+eps - Gamma_ii) - d_i ; inv = 1/Dg ; y0 = inv*rhs
    u64 inv[8], y[8];
#pragma unroll
    for (int q = 0; q < 8; ++q) {
        float g0, g1; unpack2(sGd2[q], g0, g1);      // smem (tiny)
        float d0, d1; unpack2(dd[q], d0, d1);
        inv[q] = pack2(frcp(g0 - d0), frcp(g1 - d1));
        y[q]   = mul2(inv[q], rhs[q]);
    }

    // ---- Phase 3: Neumann iterations  acc = rhs + GammaOff*y ; y = inv (*) acc
    // Off2 from smem -> these 128 loads/thread leave the constant port.
#pragma unroll
    for (int it = 0; it < ITERS; ++it) {
        u64 acc[8];
#pragma unroll
        for (int q = 0; q < 8; ++q) acc[q] = rhs[q];
#pragma unroll
        for (int j = 0; j < NDEP; ++j) {
            float a0, a1; unpack2(y[j >> 1], a0, a1);
            u64 yd = dup2((j & 1) ? a1 : a0);
#pragma unroll
            for (int q2 = 0; q2 < 4; ++q2) {
                ulonglong2 o = sOff2[j][q2];
                acc[2 * q2]     = ffma2(yd, o.x, acc[2 * q2]);
                acc[2 * q2 + 1] = ffma2(yd, o.y, acc[2 * q2 + 1]);
            }
        }
#pragma unroll
        for (int q = 0; q < 8; ++q) y[q] = mul2(inv[q], acc[q]);
    }

    // ---- Store: row-packed pairs are already in output order -> STG.128
    ulonglong2* ov = (ulonglong2*)(out + (base + tid) * NDEP);
#pragma unroll
    for (int q = 0; q < 4; ++q) ov[q] = make_ulonglong2(y[2 * q], y[2 * q + 1]);
}

extern "C" void kernel_launch(void* const* d_in, const int* in_sizes, int n_in,
                              void* d_out, int out_size)
{
    const float* X  = (const float*)d_in[0];
    const float* Z  = (const float*)d_in[1];
    const float* Up = (const float*)d_in[2];
    const float* Bm = (const float*)d_in[3];
    const float* Th = (const float*)d_in[4];
    const float* Ga = (const float*)d_in[5];
    const float* La = (const float*)d_in[6];
    float* out = (float*)d_out;

    // 1) transform weights into device scratch
    prep_kernel<<<1, 64>>>(Up, Bm, Th, Ga, La);

    // 2) copy transformed weights into the constant bank (D2D, capturable)
    void* sp = nullptr;
    cudaGetSymbolAddress(&sp, g_scratch);
    cudaMemcpyToSymbolAsync(cw, sp, sizeof(CWeights), 0,
                            cudaMemcpyDeviceToDevice, 0);

    // 3) main kernel: one element per thread
    const int blocks = BATCH / TPB;
    clefo_kernel<<<blocks, TPB>>>(X, Z, (const CWeights*)sp, out);
}